// round 12
// baseline (speedup 1.0000x reference)
#include <cuda_runtime.h>
#include <cstdint>

// ============================================================================
// out[8192,4096] = sign(x[8192,4096]) @ sign(w[4096,4096])
// Pure XOR+CSA popcount GEMM (alu pipe), exact:  dot = 4096 - 2*popc(x^w).
// R11:
//  - acc += popc  forced to IMAD (fma pipe) via opaque multiplier -> -8% alu ops
//  - persistent blocks (296) with resident A tile, B double-buffered (96KB)
//  - fused pack kernel (one launch)
// ============================================================================

static constexpr int MDIM = 8192;
static constexpr int NDIM = 4096;
static constexpr int KDIM = 4096;
static constexpr int KW   = KDIM / 32;     // 128 words per row

static constexpr int MT = MDIM / 64;       // 128
static constexpr int NT = NDIM / 64;       // 64
static constexpr int TILES = MT * NT;      // 8192
static constexpr int GRIDP = 296;          // persistent blocks (2/SM x 148)
static constexpr int TILE_WORDS = KW * 64; // 8192 words = 32KB

// Packed bit scratch, word-major per tile:
//   g_xbits[mt][w][m], g_wbits[nt][w][n]
__device__ __align__(16) uint32_t g_xbits[(size_t)MT * TILE_WORDS];   // 4 MB
__device__ __align__(16) uint32_t g_wbits[(size_t)NT * TILE_WORDS];   // 2 MB

// ---------------------------------------------------------------------------
__device__ __forceinline__ uint32_t smem_u32(const void* p) {
    uint32_t a;
    asm("{ .reg .u64 t; cvta.to.shared.u64 t, %1; cvt.u32.u64 %0, t; }" : "=r"(a) : "l"(p));
    return a;
}
__device__ __forceinline__ void cpasync16(uint32_t s, const void* g) {
    asm volatile("cp.async.cg.shared.global [%0], [%1], 16;" :: "r"(s), "l"(g));
}
#define CP_COMMIT() asm volatile("cp.async.commit_group;" ::: "memory")
#define CP_WAITN(n) asm volatile("cp.async.wait_group %0;" :: "n"(n) : "memory")

// ---------------------------------------------------------------------------
// Fused prepass: blocks [0,1024) pack x (ballot per row-warp);
//                blocks [1024,3072) pack w transposed (coalesced stores).
// ---------------------------------------------------------------------------
__global__ void __launch_bounds__(256) k_pack(const float* __restrict__ x,
                                             const float* __restrict__ w) {
    if (blockIdx.x < 1024) {
        int m    = blockIdx.x * 8 + (threadIdx.x >> 5);    // 0..8191
        int lane = threadIdx.x & 31;
        const float* row = x + (size_t)m * KDIM;
        uint32_t mt = (uint32_t)m >> 6, ml = (uint32_t)m & 63u;
        uint32_t* dst = g_xbits + (size_t)mt * TILE_WORDS + ml;
        #pragma unroll 4
        for (int wi = 0; wi < KW; wi++) {
            float v = row[wi * 32 + lane];
            uint32_t bits = __ballot_sync(0xffffffffu, v < 0.0f);
            if (lane == 0) dst[(size_t)wi * 64] = bits;
        }
    } else {
        uint32_t q  = (blockIdx.x - 1024u) * 256u + threadIdx.x;  // 0..524287
        uint32_t nl = q & 63u;
        uint32_t W  = (q >> 6) & 127u;
        uint32_t nt = q >> 13;
        uint32_t n  = nt * 64u + nl;
        uint32_t kb = W * 32u;
        uint32_t bits = 0;
        #pragma unroll
        for (int j = 0; j < 32; j++) {
            float v = w[(size_t)(kb + j) * NDIM + n];
            bits |= (v < 0.0f ? 1u : 0u) << j;
        }
        g_wbits[q] = bits;
    }
}

// ---------------------------------------------------------------------------
// Persistent binary GEMM: 296 blocks, each owns a contiguous tile range
// (row-major), A tile resident in smem, B double-buffered via cp.async.
// 256 threads, 16 outputs/thread (4m x 4n) per 64x64 tile.
// ---------------------------------------------------------------------------
__global__ void __launch_bounds__(256, 2) k_bgemm(float* __restrict__ out) {
    extern __shared__ uint32_t sm[];        // A: 8192 | B0: 8192 | B1: 8192
    uint32_t* smA  = sm;
    uint32_t* smB0 = sm + TILE_WORDS;
    uint32_t* smB1 = sm + 2 * TILE_WORDS;
    const uint32_t sbA  = smem_u32(smA);
    const uint32_t sbB0 = smem_u32(smB0);
    const uint32_t sbB1 = smem_u32(smB1);

    const int tid  = threadIdx.x;
    const int warp = tid >> 5;
    const int lane = tid & 31;
    const int mrow = (warp >> 2) * 32 + (lane >> 2) * 4;
    const int ncol = (warp & 3) * 16 + (lane & 3) * 4;

    // Opaque 1 for IMAD accumulate (compiler cannot constant-fold).
    const uint32_t one = (blockIdx.x >> 28) + 1u;

    const int p = (int)blockIdx.x;
    const int startT = (int)(((long long)p * TILES) / GRIDP);
    const int endT   = (int)(((long long)(p + 1) * TILES) / GRIDP);

    auto issueA = [&](int mtb) {
        const char* g = (const char*)(g_xbits + (size_t)mtb * TILE_WORDS);
        #pragma unroll
        for (int i = 0; i < 8; i++) {
            int c = tid + i * 256;                    // 0..2047 16B chunks
            cpasync16(sbA + (uint32_t)(c * 16), g + (size_t)c * 16);
        }
    };
    auto issueB = [&](int ntb, uint32_t sb) {
        const char* g = (const char*)(g_wbits + (size_t)ntb * TILE_WORDS);
        #pragma unroll
        for (int i = 0; i < 8; i++) {
            int c = tid + i * 256;
            cpasync16(sb + (uint32_t)(c * 16), g + (size_t)c * 16);
        }
    };

    int t = startT;
    while (t < endT) {
        const int mtb = t >> 6;
        const int segEnd = min(endT, (mtb + 1) << 6);   // row boundary

        // Segment prologue: A + B(t) in one group, optional B(t+1) prefetch.
        issueA(mtb);
        issueB(t & 63, sbB0);
        CP_COMMIT();
        if (t + 1 < segEnd) { issueB((t + 1) & 63, sbB1); CP_COMMIT(); }
        if (t + 1 < segEnd) { CP_WAITN(1); } else { CP_WAITN(0); }
        __syncthreads();

        for (int u = t; u < segEnd; u++) {
            if (u > t) {
                if (u + 1 < segEnd) { CP_WAITN(1); } else { CP_WAITN(0); }
                __syncthreads();
            }
            const uint32_t* B = ((u - t) & 1) ? smB1 : smB0;

            uint32_t ones[16], twos[16];
            uint32_t acc[16];
            #pragma unroll
            for (int o = 0; o < 16; o++) { ones[o] = 0; twos[o] = 0; acc[o] = 0; }

            #pragma unroll 8
            for (int grp = 0; grp < 32; grp++) {
                const int gw = grp * 4;
                uint32_t av[4][4], bv[4][4];
                #pragma unroll
                for (int w4 = 0; w4 < 4; w4++) {
                    uint4 A4 = *reinterpret_cast<const uint4*>(smA + (gw + w4) * 64 + mrow);
                    uint4 B4 = *reinterpret_cast<const uint4*>(B   + (gw + w4) * 64 + ncol);
                    av[0][w4] = A4.x; av[1][w4] = A4.y; av[2][w4] = A4.z; av[3][w4] = A4.w;
                    bv[0][w4] = B4.x; bv[1][w4] = B4.y; bv[2][w4] = B4.z; bv[3][w4] = B4.w;
                }
                #pragma unroll
                for (int mf = 0; mf < 4; mf++) {
                    #pragma unroll
                    for (int nf = 0; nf < 4; nf++) {
                        const int o = mf * 4 + nf;
                        uint32_t x0 = av[mf][0] ^ bv[nf][0];
                        uint32_t x1 = av[mf][1] ^ bv[nf][1];
                        uint32_t x2 = av[mf][2] ^ bv[nf][2];
                        uint32_t x3 = av[mf][3] ^ bv[nf][3];
                        uint32_t t0 = (ones[o] & x0) | (ones[o] & x1) | (x0 & x1);
                        ones[o] = ones[o] ^ x0 ^ x1;
                        uint32_t t1 = (ones[o] & x2) | (ones[o] & x3) | (x2 & x3);
                        ones[o] = ones[o] ^ x2 ^ x3;
                        uint32_t f = (twos[o] & t0) | (twos[o] & t1) | (t0 & t1);
                        twos[o] = twos[o] ^ t0 ^ t1;
                        // acc += popc(f) on the FMA pipe (IMAD), not IADD3.
                        uint32_t pc = (uint32_t)__popc(f);
                        asm("mad.lo.u32 %0, %1, %2, %0;" : "+r"(acc[o]) : "r"(pc), "r"(one));
                    }
                }
            }

            // Epilogue: D = 4*acc + 2*popc(twos) + popc(ones); dot = K - 2D.
            const uint32_t m0 = (uint32_t)mtb * 64u + (uint32_t)mrow;
            const uint32_t n0 = (uint32_t)(u & 63) * 64u + (uint32_t)ncol;
            #pragma unroll
            for (int mf = 0; mf < 4; mf++) {
                const int o = mf * 4;
                int D0 = ((int)acc[o+0] << 2) + (__popc(twos[o+0]) << 1) + __popc(ones[o+0]);
                int D1 = ((int)acc[o+1] << 2) + (__popc(twos[o+1]) << 1) + __popc(ones[o+1]);
                int D2 = ((int)acc[o+2] << 2) + (__popc(twos[o+2]) << 1) + __popc(ones[o+2]);
                int D3 = ((int)acc[o+3] << 2) + (__popc(twos[o+3]) << 1) + __popc(ones[o+3]);
                *reinterpret_cast<float4*>(out + (size_t)(m0 + (uint32_t)mf) * NDIM + n0) =
                    make_float4((float)(KDIM - 2 * D0), (float)(KDIM - 2 * D1),
                                (float)(KDIM - 2 * D2), (float)(KDIM - 2 * D3));
            }

            __syncthreads();   // all warps done reading B-buf (and smA for last u)
            if (u + 2 < segEnd) {
                issueB((u + 2) & 63, ((u - t) & 1) ? sbB1 : sbB0);
                CP_COMMIT();
            }
        }
        t = segEnd;
    }
}

// ---------------------------------------------------------------------------
// Launch
// ---------------------------------------------------------------------------
extern "C" void kernel_launch(void* const* d_in, const int* in_sizes, int n_in,
                              void* d_out, int out_size) {
    const float* x = (const float*)d_in[0];   // [8192, 4096]
    const float* w = (const float*)d_in[1];   // [4096, 4096] (k-major)
    float* out = (float*)d_out;               // [8192, 4096]
    (void)in_sizes; (void)n_in; (void)out_size;

    static constexpr int SMEM = 3 * TILE_WORDS * 4;   // 98304 B
    cudaFuncSetAttribute(k_bgemm, cudaFuncAttributeMaxDynamicSharedMemorySize, SMEM);

    k_pack<<<3072, 256>>>(x, w);
    k_bgemm<<<GRIDP, 256, SMEM>>>(out);
}

// round 13
// speedup vs baseline: 1.0397x; 1.0397x over previous
#include <cuda_runtime.h>
#include <cstdint>

// ============================================================================
// out[8192,4096] = sign(x[8192,4096]) @ sign(w[4096,4096])
//
// Pure XOR+CSA popcount GEMM, exact:  dot = 4096 - 2*popc(x^w).
// R12 = R7 block-per-tile structure (best: 964us) with:
//   - accumulate moved to the FMA pipe (IMAD via opaque multiplier): -9% alu ops
//   - fused pack prepass (one launch)
// Profile-verified: alu-pipe-bound (89%), DRAM 1%; this targets the only
// remaining reducible alu-op class.
// ============================================================================

static constexpr int MDIM = 8192;
static constexpr int NDIM = 4096;
static constexpr int KDIM = 4096;
static constexpr int KW   = KDIM / 32;   // 128 words per row

static constexpr int MT = MDIM / 64;     // 128 tiles (64 rows)
static constexpr int NT = NDIM / 64;     // 64 tiles (64 cols)

// Packed bit scratch, word-major per tile:
//   g_xbits[mt][w][m]  (mt<128, w<128, m<64)
//   g_wbits[nt][w][n]  (nt<64,  w<128, n<64)
__device__ __align__(16) uint32_t g_xbits[(size_t)MT * KW * 64];   // 4 MB
__device__ __align__(16) uint32_t g_wbits[(size_t)NT * KW * 64];   // 2 MB

// ---------------------------------------------------------------------------
__device__ __forceinline__ uint32_t smem_u32(const void* p) {
    uint32_t a;
    asm("{ .reg .u64 t; cvta.to.shared.u64 t, %1; cvt.u32.u64 %0, t; }" : "=r"(a) : "l"(p));
    return a;
}
__device__ __forceinline__ void cpasync16(uint32_t s, const void* g) {
    asm volatile("cp.async.cg.shared.global [%0], [%1], 16;" :: "r"(s), "l"(g));
}
#define CP_COMMIT() asm volatile("cp.async.commit_group;" ::: "memory")
#define CP_WAITN(n) asm volatile("cp.async.wait_group %0;" :: "n"(n) : "memory")

// ---------------------------------------------------------------------------
// Fused prepass: blocks [0,1024) pack x (ballot, one warp per row);
//                blocks [1024,3072) pack w transposed (coalesced stores).
// ---------------------------------------------------------------------------
__global__ void __launch_bounds__(256) k_pack(const float* __restrict__ x,
                                             const float* __restrict__ w) {
    if (blockIdx.x < 1024) {
        int m    = blockIdx.x * 8 + (threadIdx.x >> 5);    // 0..8191
        int lane = threadIdx.x & 31;
        const float* row = x + (size_t)m * KDIM;
        uint32_t mt = (uint32_t)m >> 6, ml = (uint32_t)m & 63u;
        uint32_t* dst = g_xbits + (size_t)mt * (KW * 64) + ml;
        #pragma unroll 4
        for (int wi = 0; wi < KW; wi++) {
            float v = row[wi * 32 + lane];
            uint32_t bits = __ballot_sync(0xffffffffu, v < 0.0f);
            if (lane == 0) dst[(size_t)wi * 64] = bits;
        }
    } else {
        uint32_t q  = (blockIdx.x - 1024u) * 256u + threadIdx.x;  // 0..524287
        uint32_t nl = q & 63u;
        uint32_t W  = (q >> 6) & 127u;
        uint32_t nt = q >> 13;
        uint32_t n  = nt * 64u + nl;
        uint32_t kb = W * 32u;
        uint32_t bits = 0;
        #pragma unroll
        for (int j = 0; j < 32; j++) {
            float v = w[(size_t)(kb + j) * NDIM + n];
            bits |= (v < 0.0f ? 1u : 0u) << j;
        }
        g_wbits[q] = bits;
    }
}

// ---------------------------------------------------------------------------
// Binary GEMM: 64x64 tile per block, 256 threads, 16 outputs/thread (4m x 4n).
// Whole K (128 words) resident in smem; halves arrive via 2 cp.async groups.
// ---------------------------------------------------------------------------
__global__ void __launch_bounds__(256, 2) k_bgemm(float* __restrict__ out) {
    extern __shared__ uint32_t sm[];                 // [A: 128*64 | B: 128*64]
    uint32_t* smA = sm;
    uint32_t* smB = sm + KW * 64;
    const uint32_t sbA = smem_u32(smA);
    const uint32_t sbB = smem_u32(smB);

    const int tid  = threadIdx.x;
    const int warp = tid >> 5;
    const int lane = tid & 31;
    const int mrow = (warp >> 2) * 32 + ((lane >> 2) * 4);   // 4 consecutive m rows
    const int ncol = (warp & 3) * 16 + ((lane & 3) * 4);     // 4 consecutive n cols

    const uint32_t bid = blockIdx.x;
    const uint32_t ntb = bid & 63u;
    const uint32_t mtb = bid >> 6;

    // Opaque 1 so the accumulate is IMAD (fma pipe), not IADD3 (alu pipe).
    const uint32_t one = (bid >> 28) + 1u;

    const char* aG = (const char*)(g_xbits + (size_t)mtb * (KW * 64));
    const char* bG = (const char*)(g_wbits + (size_t)ntb * (KW * 64));

    // Issue both halves: half h = words [h*64, h*64+64), 16KB per matrix.
    #pragma unroll
    for (int h = 0; h < 2; h++) {
        #pragma unroll
        for (int i = 0; i < 4; i++) {
            int c = tid + i * 256;                   // 0..1023 16B-chunks
            cpasync16(sbA + (uint32_t)(h * 16384 + c * 16), aG + (size_t)h * 16384 + (size_t)c * 16);
            cpasync16(sbB + (uint32_t)(h * 16384 + c * 16), bG + (size_t)h * 16384 + (size_t)c * 16);
        }
        CP_COMMIT();
    }

    uint32_t ones[16], twos[16], acc[16];
    #pragma unroll
    for (int o = 0; o < 16; o++) { ones[o] = 0; twos[o] = 0; acc[o] = 0; }

    CP_WAITN(1);
    __syncthreads();

    #pragma unroll 2
    for (int half = 0; half < 2; half++) {
        if (half == 1) { CP_WAITN(0); __syncthreads(); }

        #pragma unroll 8
        for (int grp = 0; grp < 16; grp++) {
            const int gw = half * 64 + grp * 4;      // first word of group
            uint32_t av[4][4], bv[4][4];
            #pragma unroll
            for (int w4 = 0; w4 < 4; w4++) {
                uint4 A = *reinterpret_cast<const uint4*>(smA + (gw + w4) * 64 + mrow);
                uint4 B = *reinterpret_cast<const uint4*>(smB + (gw + w4) * 64 + ncol);
                av[0][w4] = A.x; av[1][w4] = A.y; av[2][w4] = A.z; av[3][w4] = A.w;
                bv[0][w4] = B.x; bv[1][w4] = B.y; bv[2][w4] = B.z; bv[3][w4] = B.w;
            }
            #pragma unroll
            for (int mf = 0; mf < 4; mf++) {
                #pragma unroll
                for (int nf = 0; nf < 4; nf++) {
                    const int o = mf * 4 + nf;
                    uint32_t x0 = av[mf][0] ^ bv[nf][0];
                    uint32_t x1 = av[mf][1] ^ bv[nf][1];
                    uint32_t x2 = av[mf][2] ^ bv[nf][2];
                    uint32_t x3 = av[mf][3] ^ bv[nf][3];
                    // CSA(ones, x0, x1) -> t0
                    uint32_t t0 = (ones[o] & x0) | (ones[o] & x1) | (x0 & x1);
                    ones[o] = ones[o] ^ x0 ^ x1;
                    // CSA(ones, x2, x3) -> t1
                    uint32_t t1 = (ones[o] & x2) | (ones[o] & x3) | (x2 & x3);
                    ones[o] = ones[o] ^ x2 ^ x3;
                    // CSA(twos, t0, t1) -> f (weight 4)
                    uint32_t f = (twos[o] & t0) | (twos[o] & t1) | (t0 & t1);
                    twos[o] = twos[o] ^ t0 ^ t1;
                    // acc += popc(f) on the FMA pipe (IMAD).
                    uint32_t pc = (uint32_t)__popc(f);
                    asm("mad.lo.u32 %0, %1, %2, %0;" : "+r"(acc[o]) : "r"(pc), "r"(one));
                }
            }
        }
    }

    // Epilogue: D = 4*acc + 2*popc(twos) + popc(ones); dot = 4096 - 2D.
    const uint32_t m0 = mtb * 64u + (uint32_t)mrow;
    const uint32_t n0 = ntb * 64u + (uint32_t)ncol;
    #pragma unroll
    for (int mf = 0; mf < 4; mf++) {
        const int o = mf * 4;
        int D0 = ((int)acc[o+0] << 2) + (__popc(twos[o+0]) << 1) + __popc(ones[o+0]);
        int D1 = ((int)acc[o+1] << 2) + (__popc(twos[o+1]) << 1) + __popc(ones[o+1]);
        int D2 = ((int)acc[o+2] << 2) + (__popc(twos[o+2]) << 1) + __popc(ones[o+2]);
        int D3 = ((int)acc[o+3] << 2) + (__popc(twos[o+3]) << 1) + __popc(ones[o+3]);
        *reinterpret_cast<float4*>(out + (size_t)(m0 + (uint32_t)mf) * NDIM + n0) =
            make_float4((float)(KDIM - 2 * D0), (float)(KDIM - 2 * D1),
                        (float)(KDIM - 2 * D2), (float)(KDIM - 2 * D3));
    }
}

// ---------------------------------------------------------------------------
// Launch
// ---------------------------------------------------------------------------
extern "C" void kernel_launch(void* const* d_in, const int* in_sizes, int n_in,
                              void* d_out, int out_size) {
    const float* x = (const float*)d_in[0];   // [8192, 4096]
    const float* w = (const float*)d_in[1];   // [4096, 4096] (k-major)
    float* out = (float*)d_out;               // [8192, 4096]
    (void)in_sizes; (void)n_in; (void)out_size;

    static constexpr int SMEM = 2 * KW * 64 * 4;   // 65536 B
    cudaFuncSetAttribute(k_bgemm, cudaFuncAttributeMaxDynamicSharedMemorySize, SMEM);

    k_pack<<<3072, 256>>>(x, w);                   // fused x+w pack
    k_bgemm<<<MT * NT, 256, SMEM>>>(out);          // 8192 blocks
}

// round 14
// speedup vs baseline: 1.1003x; 1.0582x over previous
#include <cuda_runtime.h>
#include <cstdint>

// ============================================================================
// out[8192,4096] = sign(x[8192,4096]) @ sign(w[4096,4096])
//
// Binary GEMM, exact:  dot = 4096 - 2*popc(xbits ^ wbits).
// R13: PROFILE-DERIVED FINDING: POPC is full-rate (rt2) on sm_103's alu pipe
// (R12 metrics exclude rt8: alu-busy would exceed 100%). The Harley-Seal CSA
// tree therefore wastes LOP3s to save same-cost POPCs. New inner loop:
//   per word-pair: XOR (alu) + POPC (alu) + IMAD accumulate (fma pipe)
// alu ops/word-pair: 2.75 -> 2.0 (-27%).
// ============================================================================

static constexpr int MDIM = 8192;
static constexpr int NDIM = 4096;
static constexpr int KDIM = 4096;
static constexpr int KW   = KDIM / 32;   // 128 words per row

static constexpr int MT = MDIM / 64;     // 128 tiles (64 rows)
static constexpr int NT = NDIM / 64;     // 64 tiles (64 cols)

// Packed bit scratch, word-major per tile:
//   g_xbits[mt][w][m]  (mt<128, w<128, m<64)
//   g_wbits[nt][w][n]  (nt<64,  w<128, n<64)
__device__ __align__(16) uint32_t g_xbits[(size_t)MT * KW * 64];   // 4 MB
__device__ __align__(16) uint32_t g_wbits[(size_t)NT * KW * 64];   // 2 MB

// ---------------------------------------------------------------------------
__device__ __forceinline__ uint32_t smem_u32(const void* p) {
    uint32_t a;
    asm("{ .reg .u64 t; cvta.to.shared.u64 t, %1; cvt.u32.u64 %0, t; }" : "=r"(a) : "l"(p));
    return a;
}
__device__ __forceinline__ void cpasync16(uint32_t s, const void* g) {
    asm volatile("cp.async.cg.shared.global [%0], [%1], 16;" :: "r"(s), "l"(g));
}
#define CP_COMMIT() asm volatile("cp.async.commit_group;" ::: "memory")
#define CP_WAITN(n) asm volatile("cp.async.wait_group %0;" :: "n"(n) : "memory")

// ---------------------------------------------------------------------------
// Fused prepass: blocks [0,1024) pack x (ballot, one warp per row);
//                blocks [1024,3072) pack w transposed (coalesced stores).
// ---------------------------------------------------------------------------
__global__ void __launch_bounds__(256) k_pack(const float* __restrict__ x,
                                             const float* __restrict__ w) {
    if (blockIdx.x < 1024) {
        int m    = blockIdx.x * 8 + (threadIdx.x >> 5);    // 0..8191
        int lane = threadIdx.x & 31;
        const float* row = x + (size_t)m * KDIM;
        uint32_t mt = (uint32_t)m >> 6, ml = (uint32_t)m & 63u;
        uint32_t* dst = g_xbits + (size_t)mt * (KW * 64) + ml;
        #pragma unroll 4
        for (int wi = 0; wi < KW; wi++) {
            float v = row[wi * 32 + lane];
            uint32_t bits = __ballot_sync(0xffffffffu, v < 0.0f);
            if (lane == 0) dst[(size_t)wi * 64] = bits;
        }
    } else {
        uint32_t q  = (blockIdx.x - 1024u) * 256u + threadIdx.x;  // 0..524287
        uint32_t nl = q & 63u;
        uint32_t W  = (q >> 6) & 127u;
        uint32_t nt = q >> 13;
        uint32_t n  = nt * 64u + nl;
        uint32_t kb = W * 32u;
        uint32_t bits = 0;
        #pragma unroll
        for (int j = 0; j < 32; j++) {
            float v = w[(size_t)(kb + j) * NDIM + n];
            bits |= (v < 0.0f ? 1u : 0u) << j;
        }
        g_wbits[q] = bits;
    }
}

// ---------------------------------------------------------------------------
// Binary GEMM: 64x64 tile per block, 256 threads, 16 outputs/thread (4m x 4n).
// Whole K (128 words) resident in smem; halves arrive via 2 cp.async groups.
// Inner loop: XOR + POPC (alu pipe) + IMAD accumulate (fma pipe).
// ---------------------------------------------------------------------------
__global__ void __launch_bounds__(256, 2) k_bgemm(float* __restrict__ out) {
    extern __shared__ uint32_t sm[];                 // [A: 128*64 | B: 128*64]
    uint32_t* smA = sm;
    uint32_t* smB = sm + KW * 64;
    const uint32_t sbA = smem_u32(smA);
    const uint32_t sbB = smem_u32(smB);

    const int tid  = threadIdx.x;
    const int warp = tid >> 5;
    const int lane = tid & 31;
    const int mrow = (warp >> 2) * 32 + ((lane >> 2) * 4);   // 4 consecutive m rows
    const int ncol = (warp & 3) * 16 + ((lane & 3) * 4);     // 4 consecutive n cols

    const uint32_t bid = blockIdx.x;
    const uint32_t ntb = bid & 63u;
    const uint32_t mtb = bid >> 6;

    // Opaque 1 so the accumulate is IMAD (fma pipe), not IADD3 (alu pipe).
    // grid = 8192 < 2^28, so (bid >> 28) == 0 always, but ptxas cannot know.
    const uint32_t one = (bid >> 28) + 1u;

    const char* aG = (const char*)(g_xbits + (size_t)mtb * (KW * 64));
    const char* bG = (const char*)(g_wbits + (size_t)ntb * (KW * 64));

    // Issue both halves: half h = words [h*64, h*64+64), 16KB per matrix.
    #pragma unroll
    for (int h = 0; h < 2; h++) {
        #pragma unroll
        for (int i = 0; i < 4; i++) {
            int c = tid + i * 256;                   // 0..1023 16B-chunks
            cpasync16(sbA + (uint32_t)(h * 16384 + c * 16), aG + (size_t)h * 16384 + (size_t)c * 16);
            cpasync16(sbB + (uint32_t)(h * 16384 + c * 16), bG + (size_t)h * 16384 + (size_t)c * 16);
        }
        CP_COMMIT();
    }

    uint32_t acc[16];
    #pragma unroll
    for (int o = 0; o < 16; o++) acc[o] = 0;

    CP_WAITN(1);
    __syncthreads();

    #pragma unroll 2
    for (int half = 0; half < 2; half++) {
        if (half == 1) { CP_WAITN(0); __syncthreads(); }

        #pragma unroll 8
        for (int grp = 0; grp < 16; grp++) {
            const int gw = half * 64 + grp * 4;      // first word of group
            uint32_t av[4][4], bv[4][4];
            #pragma unroll
            for (int w4 = 0; w4 < 4; w4++) {
                uint4 A = *reinterpret_cast<const uint4*>(smA + (gw + w4) * 64 + mrow);
                uint4 B = *reinterpret_cast<const uint4*>(smB + (gw + w4) * 64 + ncol);
                av[0][w4] = A.x; av[1][w4] = A.y; av[2][w4] = A.z; av[3][w4] = A.w;
                bv[0][w4] = B.x; bv[1][w4] = B.y; bv[2][w4] = B.z; bv[3][w4] = B.w;
            }
            #pragma unroll
            for (int mf = 0; mf < 4; mf++) {
                #pragma unroll
                for (int nf = 0; nf < 4; nf++) {
                    const int o = mf * 4 + nf;
                    #pragma unroll
                    for (int w4 = 0; w4 < 4; w4++) {
                        uint32_t x = av[mf][w4] ^ bv[nf][w4];       // alu
                        uint32_t pc = (uint32_t)__popc(x);          // alu (rt2)
                        // acc += pc on the FMA pipe (IMAD).
                        asm("mad.lo.u32 %0, %1, %2, %0;" : "+r"(acc[o]) : "r"(pc), "r"(one));
                    }
                }
            }
        }
    }

    // Epilogue: acc = total disagreements D; dot = 4096 - 2D.
    const uint32_t m0 = mtb * 64u + (uint32_t)mrow;
    const uint32_t n0 = ntb * 64u + (uint32_t)ncol;
    #pragma unroll
    for (int mf = 0; mf < 4; mf++) {
        const int o = mf * 4;
        *reinterpret_cast<float4*>(out + (size_t)(m0 + (uint32_t)mf) * NDIM + n0) =
            make_float4((float)(KDIM - 2 * (int)acc[o+0]),
                        (float)(KDIM - 2 * (int)acc[o+1]),
                        (float)(KDIM - 2 * (int)acc[o+2]),
                        (float)(KDIM - 2 * (int)acc[o+3]));
    }
}

// ---------------------------------------------------------------------------
// Launch
// ---------------------------------------------------------------------------
extern "C" void kernel_launch(void* const* d_in, const int* in_sizes, int n_in,
                              void* d_out, int out_size) {
    const float* x = (const float*)d_in[0];   // [8192, 4096]
    const float* w = (const float*)d_in[1];   // [4096, 4096] (k-major)
    float* out = (float*)d_out;               // [8192, 4096]
    (void)in_sizes; (void)n_in; (void)out_size;

    static constexpr int SMEM = 2 * KW * 64 * 4;   // 65536 B
    cudaFuncSetAttribute(k_bgemm, cudaFuncAttributeMaxDynamicSharedMemorySize, SMEM);

    k_pack<<<3072, 256>>>(x, w);                   // fused x+w pack
    k_bgemm<<<MT * NT, 256, SMEM>>>(out);          // 8192 blocks
}

// round 15
// speedup vs baseline: 1.1040x; 1.0034x over previous
#include <cuda_runtime.h>
#include <cstdint>

// ============================================================================
// out[8192,4096] = sign(x[8192,4096]) @ sign(w[4096,4096])
//
// Binary GEMM, exact:  dot = 4096 - 2*popc(xbits ^ wbits).
// R14: R13 (916us) was LATENCY-bound (alu 26%, fma 13%, issue 41%, occ 24.5%).
//  - __launch_bounds__(256,3): regs<=84 -> 3 blocks/SM -> 6 warps/SMSP
//  - popc tree-add: IADD3(pc0,pc1,pc2) + 2 IMAD -> acc chain 16cyc -> 8cyc/group
// ============================================================================

static constexpr int MDIM = 8192;
static constexpr int NDIM = 4096;
static constexpr int KDIM = 4096;
static constexpr int KW   = KDIM / 32;   // 128 words per row

static constexpr int MT = MDIM / 64;     // 128 tiles (64 rows)
static constexpr int NT = NDIM / 64;     // 64 tiles (64 cols)

// Packed bit scratch, word-major per tile:
//   g_xbits[mt][w][m]  (mt<128, w<128, m<64)
//   g_wbits[nt][w][n]  (nt<64,  w<128, n<64)
__device__ __align__(16) uint32_t g_xbits[(size_t)MT * KW * 64];   // 4 MB
__device__ __align__(16) uint32_t g_wbits[(size_t)NT * KW * 64];   // 2 MB

// ---------------------------------------------------------------------------
__device__ __forceinline__ uint32_t smem_u32(const void* p) {
    uint32_t a;
    asm("{ .reg .u64 t; cvta.to.shared.u64 t, %1; cvt.u32.u64 %0, t; }" : "=r"(a) : "l"(p));
    return a;
}
__device__ __forceinline__ void cpasync16(uint32_t s, const void* g) {
    asm volatile("cp.async.cg.shared.global [%0], [%1], 16;" :: "r"(s), "l"(g));
}
#define CP_COMMIT() asm volatile("cp.async.commit_group;" ::: "memory")
#define CP_WAITN(n) asm volatile("cp.async.wait_group %0;" :: "n"(n) : "memory")

// ---------------------------------------------------------------------------
// Fused prepass: blocks [0,1024) pack x (ballot, one warp per row);
//                blocks [1024,3072) pack w transposed (coalesced stores).
// ---------------------------------------------------------------------------
__global__ void __launch_bounds__(256) k_pack(const float* __restrict__ x,
                                             const float* __restrict__ w) {
    if (blockIdx.x < 1024) {
        int m    = blockIdx.x * 8 + (threadIdx.x >> 5);    // 0..8191
        int lane = threadIdx.x & 31;
        const float* row = x + (size_t)m * KDIM;
        uint32_t mt = (uint32_t)m >> 6, ml = (uint32_t)m & 63u;
        uint32_t* dst = g_xbits + (size_t)mt * (KW * 64) + ml;
        #pragma unroll 4
        for (int wi = 0; wi < KW; wi++) {
            float v = row[wi * 32 + lane];
            uint32_t bits = __ballot_sync(0xffffffffu, v < 0.0f);
            if (lane == 0) dst[(size_t)wi * 64] = bits;
        }
    } else {
        uint32_t q  = (blockIdx.x - 1024u) * 256u + threadIdx.x;  // 0..524287
        uint32_t nl = q & 63u;
        uint32_t W  = (q >> 6) & 127u;
        uint32_t nt = q >> 13;
        uint32_t n  = nt * 64u + nl;
        uint32_t kb = W * 32u;
        uint32_t bits = 0;
        #pragma unroll
        for (int j = 0; j < 32; j++) {
            float v = w[(size_t)(kb + j) * NDIM + n];
            bits |= (v < 0.0f ? 1u : 0u) << j;
        }
        g_wbits[q] = bits;
    }
}

// ---------------------------------------------------------------------------
// Binary GEMM: 64x64 tile per block, 256 threads, 16 outputs/thread (4m x 4n).
// Whole K (128 words) resident in smem; halves arrive via 2 cp.async groups.
// Inner: XOR (alu) + POPC (popc unit) + IADD3 tree (alu) + IMAD acc (fma).
// ---------------------------------------------------------------------------
__global__ void __launch_bounds__(256, 3) k_bgemm(float* __restrict__ out) {
    extern __shared__ uint32_t sm[];                 // [A: 128*64 | B: 128*64]
    uint32_t* smA = sm;
    uint32_t* smB = sm + KW * 64;
    const uint32_t sbA = smem_u32(smA);
    const uint32_t sbB = smem_u32(smB);

    const int tid  = threadIdx.x;
    const int warp = tid >> 5;
    const int lane = tid & 31;
    const int mrow = (warp >> 2) * 32 + ((lane >> 2) * 4);   // 4 consecutive m rows
    const int ncol = (warp & 3) * 16 + ((lane & 3) * 4);     // 4 consecutive n cols

    const uint32_t bid = blockIdx.x;
    const uint32_t ntb = bid & 63u;
    const uint32_t mtb = bid >> 6;

    // Opaque 1 so accumulates use IMAD (fma pipe), not IADD3 (alu pipe).
    const uint32_t one = (bid >> 28) + 1u;

    const char* aG = (const char*)(g_xbits + (size_t)mtb * (KW * 64));
    const char* bG = (const char*)(g_wbits + (size_t)ntb * (KW * 64));

    // Issue both halves: half h = words [h*64, h*64+64), 16KB per matrix.
    #pragma unroll
    for (int h = 0; h < 2; h++) {
        #pragma unroll
        for (int i = 0; i < 4; i++) {
            int c = tid + i * 256;                   // 0..1023 16B-chunks
            cpasync16(sbA + (uint32_t)(h * 16384 + c * 16), aG + (size_t)h * 16384 + (size_t)c * 16);
            cpasync16(sbB + (uint32_t)(h * 16384 + c * 16), bG + (size_t)h * 16384 + (size_t)c * 16);
        }
        CP_COMMIT();
    }

    uint32_t acc[16];
    #pragma unroll
    for (int o = 0; o < 16; o++) acc[o] = 0;

    CP_WAITN(1);
    __syncthreads();

    #pragma unroll 2
    for (int half = 0; half < 2; half++) {
        if (half == 1) { CP_WAITN(0); __syncthreads(); }

        #pragma unroll 8
        for (int grp = 0; grp < 16; grp++) {
            const int gw = half * 64 + grp * 4;      // first word of group
            uint32_t av[4][4], bv[4][4];
            #pragma unroll
            for (int w4 = 0; w4 < 4; w4++) {
                uint4 A = *reinterpret_cast<const uint4*>(smA + (gw + w4) * 64 + mrow);
                uint4 B = *reinterpret_cast<const uint4*>(smB + (gw + w4) * 64 + ncol);
                av[0][w4] = A.x; av[1][w4] = A.y; av[2][w4] = A.z; av[3][w4] = A.w;
                bv[0][w4] = B.x; bv[1][w4] = B.y; bv[2][w4] = B.z; bv[3][w4] = B.w;
            }
            #pragma unroll
            for (int mf = 0; mf < 4; mf++) {
                #pragma unroll
                for (int nf = 0; nf < 4; nf++) {
                    const int o = mf * 4 + nf;
                    uint32_t p0 = (uint32_t)__popc(av[mf][0] ^ bv[nf][0]);
                    uint32_t p1 = (uint32_t)__popc(av[mf][1] ^ bv[nf][1]);
                    uint32_t p2 = (uint32_t)__popc(av[mf][2] ^ bv[nf][2]);
                    uint32_t p3 = (uint32_t)__popc(av[mf][3] ^ bv[nf][3]);
                    uint32_t t = p0 + p1 + p2;       // one IADD3 (alu, headroom)
                    // two IMADs (fma pipe); acc chain 8cyc/group instead of 16
                    asm("mad.lo.u32 %0, %1, %2, %0;" : "+r"(acc[o]) : "r"(t),  "r"(one));
                    asm("mad.lo.u32 %0, %1, %2, %0;" : "+r"(acc[o]) : "r"(p3), "r"(one));
                }
            }
        }
    }

    // Epilogue: acc = total disagreements D; dot = 4096 - 2D.
    const uint32_t m0 = mtb * 64u + (uint32_t)mrow;
    const uint32_t n0 = ntb * 64u + (uint32_t)ncol;
    #pragma unroll
    for (int mf = 0; mf < 4; mf++) {
        const int o = mf * 4;
        *reinterpret_cast<float4*>(out + (size_t)(m0 + (uint32_t)mf) * NDIM + n0) =
            make_float4((float)(KDIM - 2 * (int)acc[o+0]),
                        (float)(KDIM - 2 * (int)acc[o+1]),
                        (float)(KDIM - 2 * (int)acc[o+2]),
                        (float)(KDIM - 2 * (int)acc[o+3]));
    }
}

// ---------------------------------------------------------------------------
// Launch
// ---------------------------------------------------------------------------
extern "C" void kernel_launch(void* const* d_in, const int* in_sizes, int n_in,
                              void* d_out, int out_size) {
    const float* x = (const float*)d_in[0];   // [8192, 4096]
    const float* w = (const float*)d_in[1];   // [4096, 4096] (k-major)
    float* out = (float*)d_out;               // [8192, 4096]
    (void)in_sizes; (void)n_in; (void)out_size;

    static constexpr int SMEM = 2 * KW * 64 * 4;   // 65536 B
    cudaFuncSetAttribute(k_bgemm, cudaFuncAttributeMaxDynamicSharedMemorySize, SMEM);

    k_pack<<<3072, 256>>>(x, w);                   // fused x+w pack
    k_bgemm<<<MT * NT, 256, SMEM>>>(out);          // 8192 blocks
}